// round 13
// baseline (speedup 1.0000x reference)
#include <cuda_runtime.h>
#include <cstdint>
#include <cstddef>
#include <math_constants.h>

#define BB 4
#define NN 4096
#define CC 64
#define KK 16
#define KWPB 16          // warps per knn block (512 threads, 4 queries/warp)
#define QPW 4            // queries per warp
#define MW 8             // warps per mlp block
#define MT (MW*32)

// scratch (static device globals: no allocation allowed)
__device__ int g_knn[BB*NN*KK];

// ---- packed f32x2 helpers (FFMA2: only reachable via PTX fma.rn.f32x2) ----
__device__ __forceinline__ unsigned long long pack2(float lo, float hi){
  unsigned long long v;
  asm("mov.b64 %0, {%1,%2};" : "=l"(v) : "f"(lo), "f"(hi));
  return v;
}
__device__ __forceinline__ void unpack2(unsigned long long v, float &lo, float &hi){
  asm("mov.b64 {%0,%1}, %2;" : "=f"(lo), "=f"(hi) : "l"(v));
}
__device__ __forceinline__ unsigned long long ffma2(unsigned long long a,
                                                    unsigned long long b,
                                                    unsigned long long c){
  unsigned long long d;
  asm("fma.rn.f32x2 %0, %1, %2, %3;" : "=l"(d) : "l"(a), "l"(b), "l"(c));
  return d;
}
__device__ __forceinline__ unsigned long long relu2(unsigned long long v){
  float lo, hi; unpack2(v, lo, hi);
  return pack2(fmaxf(lo, 0.f), fmaxf(hi, 0.f));
}

// ============================================================================
// Kernel 1: two-pass warp-per-4-queries exact 16-NN (unchanged from R12).
// ============================================================================
__device__ __forceinline__ void insert_hits(unsigned m, float d, int j0,
                                            float& myD, int& myI, float& worst,
                                            int lane){
  while (m){
    int src = __ffs(m) - 1; m &= m - 1;
    float cd = __shfl_sync(0xffffffffu, d, src);
    if (cd < worst){                                   // warp-uniform recheck
      unsigned em = __ballot_sync(0xffffffffu, (lane < KK) && (myD == worst));
      int leader = __ffs(em) - 1;
      if (lane == leader){ myD = cd; myI = j0 + src; }
      unsigned u = (lane < KK) ? __float_as_uint(myD) : 0u;
      worst = __uint_as_float(__reduce_max_sync(0xffffffffu, u));
    }
  }
}

__global__ __launch_bounds__(KWPB*32) void knn_warp(const float* __restrict__ xyz){
  extern __shared__ float4 s4[];               // 64KB: full point DB of one batch
  const int b = blockIdx.y;
  const float* base = xyz + (size_t)b * NN * 3;
  const int tid = threadIdx.x;
  for (int i = tid; i < NN; i += KWPB*32){
    float px = base[3*i], py = base[3*i+1], pz = base[3*i+2];
    s4[i] = make_float4(px, py, pz, fmaf(px, px, fmaf(py, py, pz*pz)));
  }
  __syncthreads();

  const int wid = tid >> 5, lane = tid & 31;
  const int qbase = (blockIdx.x * KWPB + wid) * QPW;
  const int qblk = qbase & ~31;                // 32-block containing all 4 q's

  float nx[QPW], ny[QPW], nz[QPW], qq[QPW];
  #pragma unroll
  for (int k = 0; k < QPW; k++){
    float4 qv = s4[qbase + k];
    nx[k] = -2.f*qv.x; ny[k] = -2.f*qv.y; nz[k] = -2.f*qv.z; qq[k] = qv.w;
  }

  // ---- pass A: per-lane minimum (self-contamination OK, handled by 17th) ----
  float lmin[QPW];
  #pragma unroll
  for (int k = 0; k < QPW; k++) lmin[k] = CUDART_INF_F;
  #pragma unroll 2
  for (int j0i = 0; j0i < NN; j0i += 32){
    float4 p = s4[j0i + lane];
    #pragma unroll
    for (int k = 0; k < QPW; k++){
      float d = fmaf(nx[k], p.x, fmaf(ny[k], p.y, fmaf(nz[k], p.z, qq[k] + p.w)));
      lmin[k] = fminf(lmin[k], d);
    }
  }

  // ---- tau: bitonic sort the 32 lane minima, take rank 16, nextafter-up ----
  float tp[QPW];
  {
    float v[QPW];
    #pragma unroll
    for (int k = 0; k < QPW; k++) v[k] = lmin[k];
    #pragma unroll
    for (int sz = 2; sz <= 32; sz <<= 1){
      #pragma unroll
      for (int j = (sz >> 1); j > 0; j >>= 1){
        const bool up = ((lane & sz) == 0);
        const bool lower = ((lane & j) == 0);
        const bool takeMin = (lower == up);
        #pragma unroll
        for (int k = 0; k < QPW; k++){
          float o = __shfl_xor_sync(0xffffffffu, v[k], j);
          v[k] = takeMin ? fminf(v[k], o) : fmaxf(v[k], o);
        }
      }
    }
    #pragma unroll
    for (int k = 0; k < QPW; k++){
      float t16 = __shfl_sync(0xffffffffu, v[k], 16);   // 17th smallest
      tp[k] = __uint_as_float(__float_as_uint(t16) + 1u);
    }
  }

  // ---- pass B: scan with tight sentinels ----
  float myD[QPW]; int myI[QPW]; float worst[QPW];
  #pragma unroll
  for (int k = 0; k < QPW; k++){ myD[k] = tp[k]; myI[k] = 0; worst[k] = tp[k]; }

  #pragma unroll 2
  for (int j0i = 0; j0i < NN; j0i += 32){
    float4 p = s4[j0i + lane];
    float d[QPW]; unsigned m[QPW];
    #pragma unroll
    for (int k = 0; k < QPW; k++){
      d[k] = fmaf(nx[k], p.x, fmaf(ny[k], p.y, fmaf(nz[k], p.z, qq[k] + p.w)));
      m[k] = __ballot_sync(0xffffffffu, d[k] < worst[k]);
    }
    if (j0i == qblk){                          // clear self bits (one iteration)
      #pragma unroll
      for (int k = 0; k < QPW; k++) m[k] &= ~(1u << ((qbase + k) - j0i));
    }
    #pragma unroll
    for (int k = 0; k < QPW; k++)
      if (m[k]) insert_hits(m[k], d[k], j0i, myD[k], myI[k], worst[k], lane);
  }

  if (lane < KK){
    #pragma unroll
    for (int k = 0; k < QPW; k++)
      g_knn[((size_t)b * NN + qbase + k) * KK + lane] = myI[k];
  }
}

// ============================================================================
// Kernel 2: m=16 tiled register GEMM MLP, 3 CTAs/SM.
// Warp = 1 point (16 neighbors). Lane owns channels (lane, lane+32):
// acc = 2 x 8 f32x2. h tile [64 x 16] per warp (4KB), chunk rotation
// phys(k,row) = (k + (row>>1)) & 3 -> STS.128 in 4 conflict-free phases,
// gemm reads are 16B broadcasts. Weight rows XOR-swizzled (o ^ (c&31)).
// CTA smem 67KB -> 3 CTAs/SM (24 warps/SM); regs capped 85.
// ============================================================================
__global__ __launch_bounds__(MT, 3) void mlp_kernel(
    const float* __restrict__ xyz,
    const float* __restrict__ w1,
    const float* __restrict__ w2,
    const float* __restrict__ w3,
    float* __restrict__ out)
{
  extern __shared__ float sm[];
  float* w1s  = sm;              // 256  (64 x (a,b,g,0))
  float* w2T  = sm + 256;        // 4096 swizzled [c_in][c_out ^ (c_in&31)]
  float* w3T  = w2T + 4096;      // 4096
  float* relb = w3T + 4096;      // MW * 64 = 512
  float* hb   = relb + 512;      // MW * 1024 = 8192   -> total 68608 B

  const int tid = threadIdx.x, wid = tid >> 5, lane = tid & 31;
  const int point = blockIdx.x * MW + wid;       // one point per warp
  const int b = point >> 12;
  const int n = point & (NN - 1);
  const float* xb = xyz + (size_t)b * NN * 3;

  // rel-coords fill: lanes 0..15 handle one neighbor each (hoisted LDGs)
  if (lane < KK){
    const int ng = g_knn[(size_t)point * KK + lane];
    float4 r4 = make_float4(xb[ng*3+0] - xb[n*3+0],
                            xb[ng*3+1] - xb[n*3+1],
                            xb[ng*3+2] - xb[n*3+2], 0.f);
    *reinterpret_cast<float4*>(relb + wid*64 + lane*4) = r4;
  }

  for (int t = tid; t < 256; t += MT){
    int c = t >> 2, e = t & 3;
    w1s[t] = (e < 3) ? w1[c*3 + e] : 0.f;
  }
  for (int t = tid; t < 4096; t += MT){
    int o = t >> 6, c = t & 63;
    int phys = c*64 + (o ^ (c & 31));
    w2T[phys] = w2[t];
    w3T[phys] = w3[t];
  }
  __syncthreads();

  float* h = hb + wid * 1024;
  const float4* rel4 = reinterpret_cast<const float4*>(relb + wid*64);
  const int c0 = lane, c1 = lane + 32;

  // ---- layer 1: lane fills h rows c0 and c1 (m = 0..15) ----
  {
    const float4 wa = reinterpret_cast<const float4*>(w1s)[c0];
    const float4 wb = reinterpret_cast<const float4*>(w1s)[c1];
    #pragma unroll
    for (int k = 0; k < 4; k++){
      float v0[4], v1[4];
      #pragma unroll
      for (int u = 0; u < 4; u++){
        float4 r = rel4[k*4 + u];
        v0[u] = fmaxf(fmaf(wa.x, r.x, fmaf(wa.y, r.y, wa.z*r.z)), 0.f);
        v1[u] = fmaxf(fmaf(wb.x, r.x, fmaf(wb.y, r.y, wb.z*r.z)), 0.f);
      }
      *reinterpret_cast<float4*>(h + c0*16 + (((k + (c0>>1)) & 3) << 2)) =
          make_float4(v0[0], v0[1], v0[2], v0[3]);
      *reinterpret_cast<float4*>(h + c1*16 + (((k + (c1>>1)) & 3) << 2)) =
          make_float4(v1[0], v1[1], v1[2], v1[3]);
    }
  }
  __syncwarp();

  unsigned long long accA[8], accB[8];   // channel c0 / c1, m pairs

  // ---- layer 2 ----
  #pragma unroll
  for (int i = 0; i < 8; i++){ accA[i] = 0ull; accB[i] = 0ull; }
  #pragma unroll 2
  for (int j8 = 0; j8 < 8; j8++){
    #pragma unroll
    for (int jj = 0; jj < 8; jj++){
      const int j = j8*8 + jj;
      const int jx = j & 31;
      float wa0 = w2T[j*64 + (lane ^ jx)];
      float wb0 = w2T[j*64 + 32 + (lane ^ jx)];
      unsigned long long wa = pack2(wa0, wa0);
      unsigned long long wb = pack2(wb0, wb0);
      const ulonglong2* hrow = reinterpret_cast<const ulonglong2*>(h + j*16);
      #pragma unroll
      for (int k = 0; k < 2; k++){
        // 32B read = chunks 2k, 2k+1 (logical); apply rotation per 16B chunk
        ulonglong2 hv0 = hrow[(2*k     + (j>>1)) & 3];
        ulonglong2 hv1 = hrow[(2*k + 1 + (j>>1)) & 3];
        accA[4*k]   = ffma2(wa, hv0.x, accA[4*k]);
        accA[4*k+1] = ffma2(wa, hv0.y, accA[4*k+1]);
        accA[4*k+2] = ffma2(wa, hv1.x, accA[4*k+2]);
        accA[4*k+3] = ffma2(wa, hv1.y, accA[4*k+3]);
        accB[4*k]   = ffma2(wb, hv0.x, accB[4*k]);
        accB[4*k+1] = ffma2(wb, hv0.y, accB[4*k+1]);
        accB[4*k+2] = ffma2(wb, hv1.x, accB[4*k+2]);
        accB[4*k+3] = ffma2(wb, hv1.y, accB[4*k+3]);
      }
    }
  }
  __syncwarp();                 // all layer-2 reads done before overwrite

  // relu writeback of rows c0, c1 (same rotation)
  #pragma unroll
  for (int k = 0; k < 2; k++){
    ulonglong2 v;
    v.x = relu2(accA[4*k]);   v.y = relu2(accA[4*k+1]);
    *reinterpret_cast<ulonglong2*>(h + c0*16 + (((2*k   + (c0>>1)) & 3) << 2)) = v;
    v.x = relu2(accA[4*k+2]); v.y = relu2(accA[4*k+3]);
    *reinterpret_cast<ulonglong2*>(h + c0*16 + (((2*k+1 + (c0>>1)) & 3) << 2)) = v;
    v.x = relu2(accB[4*k]);   v.y = relu2(accB[4*k+1]);
    *reinterpret_cast<ulonglong2*>(h + c1*16 + (((2*k   + (c1>>1)) & 3) << 2)) = v;
    v.x = relu2(accB[4*k+2]); v.y = relu2(accB[4*k+3]);
    *reinterpret_cast<ulonglong2*>(h + c1*16 + (((2*k+1 + (c1>>1)) & 3) << 2)) = v;
  }
  __syncwarp();

  // ---- layer 3 + fused max-pool over neighbors ----
  #pragma unroll
  for (int i = 0; i < 8; i++){ accA[i] = 0ull; accB[i] = 0ull; }
  #pragma unroll 2
  for (int j8 = 0; j8 < 8; j8++){
    #pragma unroll
    for (int jj = 0; jj < 8; jj++){
      const int j = j8*8 + jj;
      const int jx = j & 31;
      float wa0 = w3T[j*64 + (lane ^ jx)];
      float wb0 = w3T[j*64 + 32 + (lane ^ jx)];
      unsigned long long wa = pack2(wa0, wa0);
      unsigned long long wb = pack2(wb0, wb0);
      const ulonglong2* hrow = reinterpret_cast<const ulonglong2*>(h + j*16);
      #pragma unroll
      for (int k = 0; k < 2; k++){
        ulonglong2 hv0 = hrow[(2*k     + (j>>1)) & 3];
        ulonglong2 hv1 = hrow[(2*k + 1 + (j>>1)) & 3];
        accA[4*k]   = ffma2(wa, hv0.x, accA[4*k]);
        accA[4*k+1] = ffma2(wa, hv0.y, accA[4*k+1]);
        accA[4*k+2] = ffma2(wa, hv1.x, accA[4*k+2]);
        accA[4*k+3] = ffma2(wa, hv1.y, accA[4*k+3]);
        accB[4*k]   = ffma2(wb, hv0.x, accB[4*k]);
        accB[4*k+1] = ffma2(wb, hv0.y, accB[4*k+1]);
        accB[4*k+2] = ffma2(wb, hv1.x, accB[4*k+2]);
        accB[4*k+3] = ffma2(wb, hv1.y, accB[4*k+3]);
      }
    }
  }
  float v0 = -CUDART_INF_F, v1 = -CUDART_INF_F;
  #pragma unroll
  for (int i = 0; i < 8; i++){
    float lo, hi;
    unpack2(accA[i], lo, hi); v0 = fmaxf(v0, fmaxf(lo, hi));
    unpack2(accB[i], lo, hi); v1 = fmaxf(v1, fmaxf(lo, hi));
  }
  out[((size_t)b*CC + c0) * NN + n] = v0;
  out[((size_t)b*CC + c1) * NN + n] = v1;
}

// ============================================================================
extern "C" void kernel_launch(void* const* d_in, const int* in_sizes, int n_in,
                              void* d_out, int out_size)
{
  const float* xyz = (const float*)d_in[0];
  const float* w1  = (const float*)d_in[1];
  const float* w2  = (const float*)d_in[2];
  const float* w3  = (const float*)d_in[3];
  float* out = (float*)d_out;
  (void)in_sizes; (void)n_in; (void)out_size;

  size_t ksmem = (size_t)NN * sizeof(float4);   // 64KB
  cudaFuncSetAttribute(knn_warp, cudaFuncAttributeMaxDynamicSharedMemorySize, (int)ksmem);
  knn_warp<<<dim3(NN/(QPW*KWPB), BB), KWPB*32, ksmem>>>(xyz);

  size_t msmem = (size_t)(256 + 4096 + 4096 + 512 + 8192) * sizeof(float); // 68608 B
  cudaFuncSetAttribute(mlp_kernel, cudaFuncAttributeMaxDynamicSharedMemorySize, (int)msmem);
  mlp_kernel<<<(BB*NN)/MW, MT, msmem>>>(xyz, w1, w2, w3, out);
}

// round 14
// speedup vs baseline: 1.0579x; 1.0579x over previous
#include <cuda_runtime.h>
#include <cstdint>
#include <cstddef>
#include <math_constants.h>

#define BB 4
#define NN 4096
#define CC 64
#define KK 16
#define KWPB 16          // warps per knn block (512 threads, 4 queries/warp)
#define QPW 4            // queries per warp
#define MW 8             // warps per mlp block
#define MT (MW*32)

// scratch (static device globals: no allocation allowed)
__device__ int g_knn[BB*NN*KK];

// ---- packed f32x2 helpers (FFMA2: only reachable via PTX fma.rn.f32x2) ----
__device__ __forceinline__ unsigned long long pack2(float lo, float hi){
  unsigned long long v;
  asm("mov.b64 %0, {%1,%2};" : "=l"(v) : "f"(lo), "f"(hi));
  return v;
}
__device__ __forceinline__ void unpack2(unsigned long long v, float &lo, float &hi){
  asm("mov.b64 {%0,%1}, %2;" : "=f"(lo), "=f"(hi) : "l"(v));
}
__device__ __forceinline__ unsigned long long ffma2(unsigned long long a,
                                                    unsigned long long b,
                                                    unsigned long long c){
  unsigned long long d;
  asm("fma.rn.f32x2 %0, %1, %2, %3;" : "=l"(d) : "l"(a), "l"(b), "l"(c));
  return d;
}
__device__ __forceinline__ unsigned long long relu2(unsigned long long v){
  float lo, hi; unpack2(v, lo, hi);
  return pack2(fmaxf(lo, 0.f), fmaxf(hi, 0.f));
}

// ============================================================================
// Kernel 1: two-pass warp-per-4-queries exact 16-NN (unchanged from R12).
// ============================================================================
__device__ __forceinline__ void insert_hits(unsigned m, float d, int j0,
                                            float& myD, int& myI, float& worst,
                                            int lane){
  while (m){
    int src = __ffs(m) - 1; m &= m - 1;
    float cd = __shfl_sync(0xffffffffu, d, src);
    if (cd < worst){                                   // warp-uniform recheck
      unsigned em = __ballot_sync(0xffffffffu, (lane < KK) && (myD == worst));
      int leader = __ffs(em) - 1;
      if (lane == leader){ myD = cd; myI = j0 + src; }
      unsigned u = (lane < KK) ? __float_as_uint(myD) : 0u;
      worst = __uint_as_float(__reduce_max_sync(0xffffffffu, u));
    }
  }
}

__global__ __launch_bounds__(KWPB*32) void knn_warp(const float* __restrict__ xyz){
  extern __shared__ float4 s4[];               // 64KB: full point DB of one batch
  const int b = blockIdx.y;
  const float* base = xyz + (size_t)b * NN * 3;
  const int tid = threadIdx.x;
  for (int i = tid; i < NN; i += KWPB*32){
    float px = base[3*i], py = base[3*i+1], pz = base[3*i+2];
    s4[i] = make_float4(px, py, pz, fmaf(px, px, fmaf(py, py, pz*pz)));
  }
  __syncthreads();

  const int wid = tid >> 5, lane = tid & 31;
  const int qbase = (blockIdx.x * KWPB + wid) * QPW;
  const int qblk = qbase & ~31;                // 32-block containing all 4 q's

  float nx[QPW], ny[QPW], nz[QPW], qq[QPW];
  #pragma unroll
  for (int k = 0; k < QPW; k++){
    float4 qv = s4[qbase + k];
    nx[k] = -2.f*qv.x; ny[k] = -2.f*qv.y; nz[k] = -2.f*qv.z; qq[k] = qv.w;
  }

  // ---- pass A: per-lane minimum (self-contamination OK, handled by 17th) ----
  float lmin[QPW];
  #pragma unroll
  for (int k = 0; k < QPW; k++) lmin[k] = CUDART_INF_F;
  #pragma unroll 2
  for (int j0i = 0; j0i < NN; j0i += 32){
    float4 p = s4[j0i + lane];
    #pragma unroll
    for (int k = 0; k < QPW; k++){
      float d = fmaf(nx[k], p.x, fmaf(ny[k], p.y, fmaf(nz[k], p.z, qq[k] + p.w)));
      lmin[k] = fminf(lmin[k], d);
    }
  }

  // ---- tau: bitonic sort the 32 lane minima, take rank 16, nextafter-up ----
  float tp[QPW];
  {
    float v[QPW];
    #pragma unroll
    for (int k = 0; k < QPW; k++) v[k] = lmin[k];
    #pragma unroll
    for (int sz = 2; sz <= 32; sz <<= 1){
      #pragma unroll
      for (int j = (sz >> 1); j > 0; j >>= 1){
        const bool up = ((lane & sz) == 0);
        const bool lower = ((lane & j) == 0);
        const bool takeMin = (lower == up);
        #pragma unroll
        for (int k = 0; k < QPW; k++){
          float o = __shfl_xor_sync(0xffffffffu, v[k], j);
          v[k] = takeMin ? fminf(v[k], o) : fmaxf(v[k], o);
        }
      }
    }
    #pragma unroll
    for (int k = 0; k < QPW; k++){
      float t16 = __shfl_sync(0xffffffffu, v[k], 16);   // 17th smallest
      tp[k] = __uint_as_float(__float_as_uint(t16) + 1u);
    }
  }

  // ---- pass B: scan with tight sentinels ----
  float myD[QPW]; int myI[QPW]; float worst[QPW];
  #pragma unroll
  for (int k = 0; k < QPW; k++){ myD[k] = tp[k]; myI[k] = 0; worst[k] = tp[k]; }

  #pragma unroll 2
  for (int j0i = 0; j0i < NN; j0i += 32){
    float4 p = s4[j0i + lane];
    float d[QPW]; unsigned m[QPW];
    #pragma unroll
    for (int k = 0; k < QPW; k++){
      d[k] = fmaf(nx[k], p.x, fmaf(ny[k], p.y, fmaf(nz[k], p.z, qq[k] + p.w)));
      m[k] = __ballot_sync(0xffffffffu, d[k] < worst[k]);
    }
    if (j0i == qblk){                          // clear self bits (one iteration)
      #pragma unroll
      for (int k = 0; k < QPW; k++) m[k] &= ~(1u << ((qbase + k) - j0i));
    }
    #pragma unroll
    for (int k = 0; k < QPW; k++)
      if (m[k]) insert_hits(m[k], d[k], j0i, myD[k], myI[k], worst[k], lane);
  }

  if (lane < KK){
    #pragma unroll
    for (int k = 0; k < QPW; k++)
      g_knn[((size_t)b * NN + qbase + k) * KK + lane] = myI[k];
  }
}

// ============================================================================
// Kernel 2: m=16 tiled register GEMM MLP, 3 CTAs/SM.
// Rotation indices now use jj (inner fully-unrolled var): (j>>1)&3 ==
// (jj>>1)&3 because j8*8>>1 = 4*j8 = 0 mod 4 -> compile-time chunk offsets,
// no per-access ALU (this was R13's regression).
// ============================================================================
__global__ __launch_bounds__(MT, 3) void mlp_kernel(
    const float* __restrict__ xyz,
    const float* __restrict__ w1,
    const float* __restrict__ w2,
    const float* __restrict__ w3,
    float* __restrict__ out)
{
  extern __shared__ float sm[];
  float* w1s  = sm;              // 256  (64 x (a,b,g,0))
  float* w2T  = sm + 256;        // 4096 swizzled [c_in][c_out ^ (c_in&31)]
  float* w3T  = w2T + 4096;      // 4096
  float* relb = w3T + 4096;      // MW * 64 = 512
  float* hb   = relb + 512;      // MW * 1024 = 8192   -> total 68608 B

  const int tid = threadIdx.x, wid = tid >> 5, lane = tid & 31;
  const int point = blockIdx.x * MW + wid;       // one point per warp
  const int b = point >> 12;
  const int n = point & (NN - 1);
  const float* xb = xyz + (size_t)b * NN * 3;

  // rel-coords fill: lanes 0..15 handle one neighbor each (hoisted LDGs)
  if (lane < KK){
    const int ng = g_knn[(size_t)point * KK + lane];
    float4 r4 = make_float4(xb[ng*3+0] - xb[n*3+0],
                            xb[ng*3+1] - xb[n*3+1],
                            xb[ng*3+2] - xb[n*3+2], 0.f);
    *reinterpret_cast<float4*>(relb + wid*64 + lane*4) = r4;
  }

  for (int t = tid; t < 256; t += MT){
    int c = t >> 2, e = t & 3;
    w1s[t] = (e < 3) ? w1[c*3 + e] : 0.f;
  }
  for (int t = tid; t < 4096; t += MT){
    int o = t >> 6, c = t & 63;
    int phys = c*64 + (o ^ (c & 31));
    w2T[phys] = w2[t];
    w3T[phys] = w3[t];
  }
  __syncthreads();

  float* h = hb + wid * 1024;
  const float4* rel4 = reinterpret_cast<const float4*>(relb + wid*64);
  const int c0 = lane, c1 = lane + 32;

  // ---- layer 1: lane fills h rows c0 and c1 (m = 0..15) ----
  {
    const float4 wa = reinterpret_cast<const float4*>(w1s)[c0];
    const float4 wb = reinterpret_cast<const float4*>(w1s)[c1];
    #pragma unroll
    for (int k = 0; k < 4; k++){
      float v0[4], v1[4];
      #pragma unroll
      for (int u = 0; u < 4; u++){
        float4 r = rel4[k*4 + u];
        v0[u] = fmaxf(fmaf(wa.x, r.x, fmaf(wa.y, r.y, wa.z*r.z)), 0.f);
        v1[u] = fmaxf(fmaf(wb.x, r.x, fmaf(wb.y, r.y, wb.z*r.z)), 0.f);
      }
      *reinterpret_cast<float4*>(h + c0*16 + (((k + (c0>>1)) & 3) << 2)) =
          make_float4(v0[0], v0[1], v0[2], v0[3]);
      *reinterpret_cast<float4*>(h + c1*16 + (((k + (c1>>1)) & 3) << 2)) =
          make_float4(v1[0], v1[1], v1[2], v1[3]);
    }
  }
  __syncwarp();

  unsigned long long accA[8], accB[8];   // channel c0 / c1, m pairs

  // ---- layer 2 ----
  #pragma unroll
  for (int i = 0; i < 8; i++){ accA[i] = 0ull; accB[i] = 0ull; }
  #pragma unroll 2
  for (int j8 = 0; j8 < 8; j8++){
    #pragma unroll
    for (int jj = 0; jj < 8; jj++){
      const int j = j8*8 + jj;
      const int jx = j & 31;
      float wa0 = w2T[j*64 + (lane ^ jx)];
      float wb0 = w2T[j*64 + 32 + (lane ^ jx)];
      unsigned long long wa = pack2(wa0, wa0);
      unsigned long long wb = pack2(wb0, wb0);
      const ulonglong2* hrow = reinterpret_cast<const ulonglong2*>(h + j*16);
      #pragma unroll
      for (int k = 0; k < 2; k++){
        // rotation depends only on jj: (j>>1)&3 == (jj>>1)&3  (compile-time)
        ulonglong2 hv0 = hrow[(2*k     + (jj>>1)) & 3];
        ulonglong2 hv1 = hrow[(2*k + 1 + (jj>>1)) & 3];
        accA[4*k]   = ffma2(wa, hv0.x, accA[4*k]);
        accA[4*k+1] = ffma2(wa, hv0.y, accA[4*k+1]);
        accA[4*k+2] = ffma2(wa, hv1.x, accA[4*k+2]);
        accA[4*k+3] = ffma2(wa, hv1.y, accA[4*k+3]);
        accB[4*k]   = ffma2(wb, hv0.x, accB[4*k]);
        accB[4*k+1] = ffma2(wb, hv0.y, accB[4*k+1]);
        accB[4*k+2] = ffma2(wb, hv1.x, accB[4*k+2]);
        accB[4*k+3] = ffma2(wb, hv1.y, accB[4*k+3]);
      }
    }
  }
  __syncwarp();                 // all layer-2 reads done before overwrite

  // relu writeback of rows c0, c1 (same rotation; k unrolled, computed once)
  #pragma unroll
  for (int k = 0; k < 2; k++){
    ulonglong2 v;
    v.x = relu2(accA[4*k]);   v.y = relu2(accA[4*k+1]);
    *reinterpret_cast<ulonglong2*>(h + c0*16 + (((2*k   + (c0>>1)) & 3) << 2)) = v;
    v.x = relu2(accA[4*k+2]); v.y = relu2(accA[4*k+3]);
    *reinterpret_cast<ulonglong2*>(h + c0*16 + (((2*k+1 + (c0>>1)) & 3) << 2)) = v;
    v.x = relu2(accB[4*k]);   v.y = relu2(accB[4*k+1]);
    *reinterpret_cast<ulonglong2*>(h + c1*16 + (((2*k   + (c1>>1)) & 3) << 2)) = v;
    v.x = relu2(accB[4*k+2]); v.y = relu2(accB[4*k+3]);
    *reinterpret_cast<ulonglong2*>(h + c1*16 + (((2*k+1 + (c1>>1)) & 3) << 2)) = v;
  }
  __syncwarp();

  // ---- layer 3 + fused max-pool over neighbors ----
  #pragma unroll
  for (int i = 0; i < 8; i++){ accA[i] = 0ull; accB[i] = 0ull; }
  #pragma unroll 2
  for (int j8 = 0; j8 < 8; j8++){
    #pragma unroll
    for (int jj = 0; jj < 8; jj++){
      const int j = j8*8 + jj;
      const int jx = j & 31;
      float wa0 = w3T[j*64 + (lane ^ jx)];
      float wb0 = w3T[j*64 + 32 + (lane ^ jx)];
      unsigned long long wa = pack2(wa0, wa0);
      unsigned long long wb = pack2(wb0, wb0);
      const ulonglong2* hrow = reinterpret_cast<const ulonglong2*>(h + j*16);
      #pragma unroll
      for (int k = 0; k < 2; k++){
        ulonglong2 hv0 = hrow[(2*k     + (jj>>1)) & 3];
        ulonglong2 hv1 = hrow[(2*k + 1 + (jj>>1)) & 3];
        accA[4*k]   = ffma2(wa, hv0.x, accA[4*k]);
        accA[4*k+1] = ffma2(wa, hv0.y, accA[4*k+1]);
        accA[4*k+2] = ffma2(wa, hv1.x, accA[4*k+2]);
        accA[4*k+3] = ffma2(wa, hv1.y, accA[4*k+3]);
        accB[4*k]   = ffma2(wb, hv0.x, accB[4*k]);
        accB[4*k+1] = ffma2(wb, hv0.y, accB[4*k+1]);
        accB[4*k+2] = ffma2(wb, hv1.x, accB[4*k+2]);
        accB[4*k+3] = ffma2(wb, hv1.y, accB[4*k+3]);
      }
    }
  }
  float v0 = -CUDART_INF_F, v1 = -CUDART_INF_F;
  #pragma unroll
  for (int i = 0; i < 8; i++){
    float lo, hi;
    unpack2(accA[i], lo, hi); v0 = fmaxf(v0, fmaxf(lo, hi));
    unpack2(accB[i], lo, hi); v1 = fmaxf(v1, fmaxf(lo, hi));
  }
  out[((size_t)b*CC + c0) * NN + n] = v0;
  out[((size_t)b*CC + c1) * NN + n] = v1;
}

// ============================================================================
extern "C" void kernel_launch(void* const* d_in, const int* in_sizes, int n_in,
                              void* d_out, int out_size)
{
  const float* xyz = (const float*)d_in[0];
  const float* w1  = (const float*)d_in[1];
  const float* w2  = (const float*)d_in[2];
  const float* w3  = (const float*)d_in[3];
  float* out = (float*)d_out;
  (void)in_sizes; (void)n_in; (void)out_size;

  size_t ksmem = (size_t)NN * sizeof(float4);   // 64KB
  cudaFuncSetAttribute(knn_warp, cudaFuncAttributeMaxDynamicSharedMemorySize, (int)ksmem);
  knn_warp<<<dim3(NN/(QPW*KWPB), BB), KWPB*32, ksmem>>>(xyz);

  size_t msmem = (size_t)(256 + 4096 + 4096 + 512 + 8192) * sizeof(float); // 68608 B
  cudaFuncSetAttribute(mlp_kernel, cudaFuncAttributeMaxDynamicSharedMemorySize, (int)msmem);
  mlp_kernel<<<(BB*NN)/MW, MT, msmem>>>(xyz, w1, w2, w3, out);
}

// round 15
// speedup vs baseline: 1.1455x; 1.0828x over previous
#include <cuda_runtime.h>
#include <cstdint>
#include <cstddef>
#include <math_constants.h>

#define BB 4
#define NN 4096
#define CC 64
#define KK 16
#define KWPB 16          // warps per knn block (512 threads, 4 queries/warp)
#define QPW 4            // queries per warp
#define MW 8             // warps per mlp block
#define MT (MW*32)

// scratch (static device globals: no allocation allowed)
__device__ int g_knn[BB*NN*KK];

// ---- packed f32x2 helpers (FFMA2: only reachable via PTX fma.rn.f32x2) ----
__device__ __forceinline__ unsigned long long pack2(float lo, float hi){
  unsigned long long v;
  asm("mov.b64 %0, {%1,%2};" : "=l"(v) : "f"(lo), "f"(hi));
  return v;
}
__device__ __forceinline__ void unpack2(unsigned long long v, float &lo, float &hi){
  asm("mov.b64 {%0,%1}, %2;" : "=f"(lo), "=f"(hi) : "l"(v));
}
__device__ __forceinline__ unsigned long long ffma2(unsigned long long a,
                                                    unsigned long long b,
                                                    unsigned long long c){
  unsigned long long d;
  asm("fma.rn.f32x2 %0, %1, %2, %3;" : "=l"(d) : "l"(a), "l"(b), "l"(c));
  return d;
}
__device__ __forceinline__ unsigned long long relu2(unsigned long long v){
  float lo, hi; unpack2(v, lo, hi);
  return pack2(fmaxf(lo, 0.f), fmaxf(hi, 0.f));
}

// ============================================================================
// Kernel 1: two-pass warp-per-4-queries exact 16-NN.
// R14 structure + fused any-hit ballot in pass B (4 ballots -> 1 in the
// common no-hit case; per-query ballots only when the warp-uniform
// any-hit fires).
// ============================================================================
__device__ __forceinline__ void insert_hits(unsigned m, float d, int j0,
                                            float& myD, int& myI, float& worst,
                                            int lane){
  while (m){
    int src = __ffs(m) - 1; m &= m - 1;
    float cd = __shfl_sync(0xffffffffu, d, src);
    if (cd < worst){                                   // warp-uniform recheck
      unsigned em = __ballot_sync(0xffffffffu, (lane < KK) && (myD == worst));
      int leader = __ffs(em) - 1;
      if (lane == leader){ myD = cd; myI = j0 + src; }
      unsigned u = (lane < KK) ? __float_as_uint(myD) : 0u;
      worst = __uint_as_float(__reduce_max_sync(0xffffffffu, u));
    }
  }
}

__global__ __launch_bounds__(KWPB*32) void knn_warp(const float* __restrict__ xyz){
  extern __shared__ float4 s4[];               // 64KB: full point DB of one batch
  const int b = blockIdx.y;
  const float* base = xyz + (size_t)b * NN * 3;
  const int tid = threadIdx.x;
  for (int i = tid; i < NN; i += KWPB*32){
    float px = base[3*i], py = base[3*i+1], pz = base[3*i+2];
    s4[i] = make_float4(px, py, pz, fmaf(px, px, fmaf(py, py, pz*pz)));
  }
  __syncthreads();

  const int wid = tid >> 5, lane = tid & 31;
  const int qbase = (blockIdx.x * KWPB + wid) * QPW;
  const int qblk = qbase & ~31;                // 32-block containing all 4 q's

  float nx[QPW], ny[QPW], nz[QPW], qq[QPW];
  #pragma unroll
  for (int k = 0; k < QPW; k++){
    float4 qv = s4[qbase + k];
    nx[k] = -2.f*qv.x; ny[k] = -2.f*qv.y; nz[k] = -2.f*qv.z; qq[k] = qv.w;
  }

  // ---- pass A: per-lane minimum (self-contamination OK, handled by 17th) ----
  float lmin[QPW];
  #pragma unroll
  for (int k = 0; k < QPW; k++) lmin[k] = CUDART_INF_F;
  #pragma unroll 2
  for (int j0i = 0; j0i < NN; j0i += 32){
    float4 p = s4[j0i + lane];
    #pragma unroll
    for (int k = 0; k < QPW; k++){
      float d = fmaf(nx[k], p.x, fmaf(ny[k], p.y, fmaf(nz[k], p.z, qq[k] + p.w)));
      lmin[k] = fminf(lmin[k], d);
    }
  }

  // ---- tau: bitonic sort the 32 lane minima, take rank 16, nextafter-up ----
  float tp[QPW];
  {
    float v[QPW];
    #pragma unroll
    for (int k = 0; k < QPW; k++) v[k] = lmin[k];
    #pragma unroll
    for (int sz = 2; sz <= 32; sz <<= 1){
      #pragma unroll
      for (int j = (sz >> 1); j > 0; j >>= 1){
        const bool up = ((lane & sz) == 0);
        const bool lower = ((lane & j) == 0);
        const bool takeMin = (lower == up);
        #pragma unroll
        for (int k = 0; k < QPW; k++){
          float o = __shfl_xor_sync(0xffffffffu, v[k], j);
          v[k] = takeMin ? fminf(v[k], o) : fmaxf(v[k], o);
        }
      }
    }
    #pragma unroll
    for (int k = 0; k < QPW; k++){
      float t16 = __shfl_sync(0xffffffffu, v[k], 16);   // 17th smallest
      tp[k] = __uint_as_float(__float_as_uint(t16) + 1u);
    }
  }

  // ---- pass B: scan with tight sentinels, fused any-hit ballot ----
  float myD[QPW]; int myI[QPW]; float worst[QPW];
  #pragma unroll
  for (int k = 0; k < QPW; k++){ myD[k] = tp[k]; myI[k] = 0; worst[k] = tp[k]; }

  #pragma unroll 2
  for (int j0i = 0; j0i < NN; j0i += 32){
    float4 p = s4[j0i + lane];
    float d[QPW];
    bool any = false;
    #pragma unroll
    for (int k = 0; k < QPW; k++){
      d[k] = fmaf(nx[k], p.x, fmaf(ny[k], p.y, fmaf(nz[k], p.z, qq[k] + p.w)));
      any |= (d[k] < worst[k]);
    }
    unsigned many = __ballot_sync(0xffffffffu, any);
    if (many){                                  // warp-uniform
      unsigned m[QPW];
      #pragma unroll
      for (int k = 0; k < QPW; k++)
        m[k] = __ballot_sync(0xffffffffu, d[k] < worst[k]);
      if (j0i == qblk){                         // clear self bits (one iteration)
        #pragma unroll
        for (int k = 0; k < QPW; k++) m[k] &= ~(1u << ((qbase + k) - j0i));
      }
      #pragma unroll
      for (int k = 0; k < QPW; k++)
        if (m[k]) insert_hits(m[k], d[k], j0i, myD[k], myI[k], worst[k], lane);
    }
  }

  if (lane < KK){
    #pragma unroll
    for (int k = 0; k < QPW; k++)
      g_knn[((size_t)b * NN + qbase + k) * KK + lane] = myI[k];
  }
}

// ============================================================================
// Kernel 2: m=16 tiled register GEMM MLP, 3 CTAs/SM, j-paired weights.
// Weight packing: wQ[g][o] = {W[o][2g], W[o+32][2g], W[o][2g+1], W[o+32][2g+1]}
// at physical index (g*32 + (o^g)), o in 0..31 -> ONE LDS.128 per lane per
// j-pair delivers all 4 weights (distinct 16B words, 4 clean wavefronts).
// h rotation (j>>1)&3 == g&3 == gg&3: compile-time, shared by both j's.
// ============================================================================
__global__ __launch_bounds__(MT, 3) void mlp_kernel(
    const float* __restrict__ xyz,
    const float* __restrict__ w1,
    const float* __restrict__ w2,
    const float* __restrict__ w3,
    float* __restrict__ out)
{
  extern __shared__ float sm[];
  float* w1s  = sm;              // 256  (64 x (a,b,g,0))
  float* w2Q  = sm + 256;        // 4096 j-pair packed (see header)
  float* w3Q  = w2Q + 4096;      // 4096
  float* relb = w3Q + 4096;      // MW * 64 = 512
  float* hb   = relb + 512;      // MW * 1024 = 8192   -> total 68608 B

  const int tid = threadIdx.x, wid = tid >> 5, lane = tid & 31;
  const int point = blockIdx.x * MW + wid;       // one point per warp
  const int b = point >> 12;
  const int n = point & (NN - 1);
  const float* xb = xyz + (size_t)b * NN * 3;

  // rel-coords fill: lanes 0..15 handle one neighbor each (hoisted LDGs)
  if (lane < KK){
    const int ng = g_knn[(size_t)point * KK + lane];
    float4 r4 = make_float4(xb[ng*3+0] - xb[n*3+0],
                            xb[ng*3+1] - xb[n*3+1],
                            xb[ng*3+2] - xb[n*3+2], 0.f);
    *reinterpret_cast<float4*>(relb + wid*64 + lane*4) = r4;
  }

  for (int t = tid; t < 256; t += MT){
    int c = t >> 2, e = t & 3;
    w1s[t] = (e < 3) ? w1[c*3 + e] : 0.f;
  }
  for (int t = tid; t < 4096; t += MT){
    int o = t >> 6, c = t & 63;                 // W[o][c]
    int g = c >> 1;
    int comp = ((c & 1) << 1) | (o >> 5);
    int phys = (g*32 + ((o & 31) ^ g))*4 + comp;
    w2Q[phys] = w2[t];
    w3Q[phys] = w3[t];
  }
  __syncthreads();

  float* h = hb + wid * 1024;
  const float4* rel4 = reinterpret_cast<const float4*>(relb + wid*64);
  const int c0 = lane, c1 = lane + 32;

  // ---- layer 1: lane fills h rows c0 and c1 (m = 0..15) ----
  {
    const float4 wa = reinterpret_cast<const float4*>(w1s)[c0];
    const float4 wb = reinterpret_cast<const float4*>(w1s)[c1];
    #pragma unroll
    for (int k = 0; k < 4; k++){
      float v0[4], v1[4];
      #pragma unroll
      for (int u = 0; u < 4; u++){
        float4 r = rel4[k*4 + u];
        v0[u] = fmaxf(fmaf(wa.x, r.x, fmaf(wa.y, r.y, wa.z*r.z)), 0.f);
        v1[u] = fmaxf(fmaf(wb.x, r.x, fmaf(wb.y, r.y, wb.z*r.z)), 0.f);
      }
      *reinterpret_cast<float4*>(h + c0*16 + (((k + (c0>>1)) & 3) << 2)) =
          make_float4(v0[0], v0[1], v0[2], v0[3]);
      *reinterpret_cast<float4*>(h + c1*16 + (((k + (c1>>1)) & 3) << 2)) =
          make_float4(v1[0], v1[1], v1[2], v1[3]);
    }
  }
  __syncwarp();

  unsigned long long accA[8], accB[8];   // channel c0 / c1, m pairs
  const float4* w2Q4 = reinterpret_cast<const float4*>(w2Q);
  const float4* w3Q4 = reinterpret_cast<const float4*>(w3Q);

  // ---- layer 2 ----
  #pragma unroll
  for (int i = 0; i < 8; i++){ accA[i] = 0ull; accB[i] = 0ull; }
  #pragma unroll 2
  for (int g8 = 0; g8 < 4; g8++){
    #pragma unroll
    for (int gg = 0; gg < 8; gg++){
      const int g = g8*8 + gg;
      float4 wv = w2Q4[g*32 + (lane ^ g)];
      unsigned long long wa0 = pack2(wv.x, wv.x);   // c0, j=2g
      unsigned long long wb0 = pack2(wv.y, wv.y);   // c1, j=2g
      unsigned long long wa1 = pack2(wv.z, wv.z);   // c0, j=2g+1
      unsigned long long wb1 = pack2(wv.w, wv.w);   // c1, j=2g+1
      const ulonglong2* hlo = reinterpret_cast<const ulonglong2*>(h + (2*g)*16);
      const ulonglong2* hhi = reinterpret_cast<const ulonglong2*>(h + (2*g+1)*16);
      #pragma unroll
      for (int k = 0; k < 2; k++){
        // rotation (j>>1)&3 == g&3 == gg&3: compile-time
        ulonglong2 l0 = hlo[(2*k     + (gg&3)) & 3];
        ulonglong2 l1 = hlo[(2*k + 1 + (gg&3)) & 3];
        ulonglong2 u0 = hhi[(2*k     + (gg&3)) & 3];
        ulonglong2 u1 = hhi[(2*k + 1 + (gg&3)) & 3];
        accA[4*k]   = ffma2(wa1, u0.x, ffma2(wa0, l0.x, accA[4*k]));
        accA[4*k+1] = ffma2(wa1, u0.y, ffma2(wa0, l0.y, accA[4*k+1]));
        accA[4*k+2] = ffma2(wa1, u1.x, ffma2(wa0, l1.x, accA[4*k+2]));
        accA[4*k+3] = ffma2(wa1, u1.y, ffma2(wa0, l1.y, accA[4*k+3]));
        accB[4*k]   = ffma2(wb1, u0.x, ffma2(wb0, l0.x, accB[4*k]));
        accB[4*k+1] = ffma2(wb1, u0.y, ffma2(wb0, l0.y, accB[4*k+1]));
        accB[4*k+2] = ffma2(wb1, u1.x, ffma2(wb0, l1.x, accB[4*k+2]));
        accB[4*k+3] = ffma2(wb1, u1.y, ffma2(wb0, l1.y, accB[4*k+3]));
      }
    }
  }
  __syncwarp();                 // all layer-2 reads done before overwrite

  // relu writeback of rows c0, c1 (same rotation)
  #pragma unroll
  for (int k = 0; k < 2; k++){
    ulonglong2 v;
    v.x = relu2(accA[4*k]);   v.y = relu2(accA[4*k+1]);
    *reinterpret_cast<ulonglong2*>(h + c0*16 + (((2*k   + (c0>>1)) & 3) << 2)) = v;
    v.x = relu2(accA[4*k+2]); v.y = relu2(accA[4*k+3]);
    *reinterpret_cast<ulonglong2*>(h + c0*16 + (((2*k+1 + (c0>>1)) & 3) << 2)) = v;
    v.x = relu2(accB[4*k]);   v.y = relu2(accB[4*k+1]);
    *reinterpret_cast<ulonglong2*>(h + c1*16 + (((2*k   + (c1>>1)) & 3) << 2)) = v;
    v.x = relu2(accB[4*k+2]); v.y = relu2(accB[4*k+3]);
    *reinterpret_cast<ulonglong2*>(h + c1*16 + (((2*k+1 + (c1>>1)) & 3) << 2)) = v;
  }
  __syncwarp();

  // ---- layer 3 + fused max-pool over neighbors ----
  #pragma unroll
  for (int i = 0; i < 8; i++){ accA[i] = 0ull; accB[i] = 0ull; }
  #pragma unroll 2
  for (int g8 = 0; g8 < 4; g8++){
    #pragma unroll
    for (int gg = 0; gg < 8; gg++){
      const int g = g8*8 + gg;
      float4 wv = w3Q4[g*32 + (lane ^ g)];
      unsigned long long wa0 = pack2(wv.x, wv.x);
      unsigned long long wb0 = pack2(wv.y, wv.y);
      unsigned long long wa1 = pack2(wv.z, wv.z);
      unsigned long long wb1 = pack2(wv.w, wv.w);
      const ulonglong2* hlo = reinterpret_cast<const ulonglong2*>(h + (2*g)*16);
      const ulonglong2* hhi = reinterpret_cast<const ulonglong2*>(h + (2*g+1)*16);
      #pragma unroll
      for (int k = 0; k < 2; k++){
        ulonglong2 l0 = hlo[(2*k     + (gg&3)) & 3];
        ulonglong2 l1 = hlo[(2*k + 1 + (gg&3)) & 3];
        ulonglong2 u0 = hhi[(2*k     + (gg&3)) & 3];
        ulonglong2 u1 = hhi[(2*k + 1 + (gg&3)) & 3];
        accA[4*k]   = ffma2(wa1, u0.x, ffma2(wa0, l0.x, accA[4*k]));
        accA[4*k+1] = ffma2(wa1, u0.y, ffma2(wa0, l0.y, accA[4*k+1]));
        accA[4*k+2] = ffma2(wa1, u1.x, ffma2(wa0, l1.x, accA[4*k+2]));
        accA[4*k+3] = ffma2(wa1, u1.y, ffma2(wa0, l1.y, accA[4*k+3]));
        accB[4*k]   = ffma2(wb1, u0.x, ffma2(wb0, l0.x, accB[4*k]));
        accB[4*k+1] = ffma2(wb1, u0.y, ffma2(wb0, l0.y, accB[4*k+1]));
        accB[4*k+2] = ffma2(wb1, u1.x, ffma2(wb0, l1.x, accB[4*k+2]));
        accB[4*k+3] = ffma2(wb1, u1.y, ffma2(wb0, l1.y, accB[4*k+3]));
      }
    }
  }
  float v0 = -CUDART_INF_F, v1 = -CUDART_INF_F;
  #pragma unroll
  for (int i = 0; i < 8; i++){
    float lo, hi;
    unpack2(accA[i], lo, hi); v0 = fmaxf(v0, fmaxf(lo, hi));
    unpack2(accB[i], lo, hi); v1 = fmaxf(v1, fmaxf(lo, hi));
  }
  out[((size_t)b*CC + c0) * NN + n] = v0;
  out[((size_t)b*CC + c1) * NN + n] = v1;
}

// ============================================================================
extern "C" void kernel_launch(void* const* d_in, const int* in_sizes, int n_in,
                              void* d_out, int out_size)
{
  const float* xyz = (const float*)d_in[0];
  const float* w1  = (const float*)d_in[1];
  const float* w2  = (const float*)d_in[2];
  const float* w3  = (const float*)d_in[3];
  float* out = (float*)d_out;
  (void)in_sizes; (void)n_in; (void)out_size;

  size_t ksmem = (size_t)NN * sizeof(float4);   // 64KB
  cudaFuncSetAttribute(knn_warp, cudaFuncAttributeMaxDynamicSharedMemorySize, (int)ksmem);
  knn_warp<<<dim3(NN/(QPW*KWPB), BB), KWPB*32, ksmem>>>(xyz);

  size_t msmem = (size_t)(256 + 4096 + 4096 + 512 + 8192) * sizeof(float); // 68608 B
  cudaFuncSetAttribute(mlp_kernel, cudaFuncAttributeMaxDynamicSharedMemorySize, (int)msmem);
  mlp_kernel<<<(BB*NN)/MW, MT, msmem>>>(xyz, w1, w2, w3, out);
}